// round 2
// baseline (speedup 1.0000x reference)
#include <cuda_runtime.h>

#define NN   50000
#define EE   800000
#define DIN  128
#define DHID 64
#define DOUT 128

// ---------------- scratch (static device globals; no allocation) ----------------
__device__ __align__(16) float g_dinv[NN];
__device__ int   g_cnt[NN];
__device__ int   g_cur[NN];
__device__ int   g_offs[NN + 1];
__device__ int   g_csr[EE];
__device__ int   g_part[256];
__device__ int   g_part2[256];
__device__ __align__(16) float g_hs [NN * DHID];   // scaled features (conv1 pre-agg / conv2 pre-agg)
__device__ __align__(16) float g_agg[NN * DHID];   // aggregation result
__device__ __align__(16) float g_tmp[NN * DOUT];   // x + h1@Wl + bl

// ---------------- CSR build ----------------
__global__ void k_init(int n) {
    int i = blockIdx.x * blockDim.x + threadIdx.x;
    if (i < n) { g_cnt[i] = 0; g_cur[i] = 0; }
}

__global__ void k_count(const int* __restrict__ dst, int e) {
    int i = blockIdx.x * blockDim.x + threadIdx.x;
    if (i < e) atomicAdd(&g_cnt[dst[i]], 1);
}

__global__ void k_scan1(int n) {
    __shared__ int sh[256];
    int t = threadIdx.x;
    int i = blockIdx.x * 256 + t;
    int v = (i < n) ? g_cnt[i] : 0;
    sh[t] = v;
    for (int off = 1; off < 256; off <<= 1) {
        __syncthreads();
        int x = (t >= off) ? sh[t - off] : 0;
        __syncthreads();
        sh[t] += x;
    }
    __syncthreads();
    if (i < n) g_offs[i] = sh[t] - v;          // block-local exclusive
    if (t == 255) g_part[blockIdx.x] = sh[255];
}

__global__ void k_scan2(int nb) {
    __shared__ int sh[256];
    int t = threadIdx.x;
    int v = (t < nb) ? g_part[t] : 0;
    sh[t] = v;
    for (int off = 1; off < 256; off <<= 1) {
        __syncthreads();
        int x = (t >= off) ? sh[t - off] : 0;
        __syncthreads();
        sh[t] += x;
    }
    __syncthreads();
    g_part2[t] = sh[t] - v;                    // exclusive block offsets
}

__global__ void k_scan3(int n, int e) {
    int i = blockIdx.x * 256 + threadIdx.x;
    if (i < n) {
        g_offs[i] += g_part2[blockIdx.x];
        g_dinv[i]  = rsqrtf((float)g_cnt[i] + 1.0f);   // deg = in-degree + self-loop
    }
    if (i == 0) g_offs[n] = e;
}

__global__ void k_fill(const int* __restrict__ src,
                       const int* __restrict__ dst, int e) {
    int i = blockIdx.x * blockDim.x + threadIdx.x;
    if (i < e) {
        int d = dst[i];
        int p = g_offs[d] + atomicAdd(&g_cur[d], 1);
        g_csr[p] = src[i];
    }
}

// ---------------- GEMM1: hs = (x @ W1) * dinv[row] ----------------
// block = 256 threads, 16 rows/block
__global__ void k_gemm1(const float* __restrict__ x, const float* __restrict__ W1, int n) {
    __shared__ float Ws[DIN * DHID];   // 32 KB
    __shared__ float xs[16 * DIN];     //  8 KB
    int t = threadIdx.x;
    int row0 = blockIdx.x * 16;
    for (int i = t; i < DIN * DHID; i += 256) Ws[i] = W1[i];
    for (int i = t; i < 16 * DIN;   i += 256) xs[i] = x[row0 * DIN + i];
    __syncthreads();
    int col = t & 63;
    int rq  = t >> 6;                  // 0..3, constant per warp
    float acc[4] = {0.f, 0.f, 0.f, 0.f};
#pragma unroll 16
    for (int k = 0; k < DIN; k++) {
        float w = Ws[k * DHID + col];
#pragma unroll
        for (int j = 0; j < 4; j++)
            acc[j] += xs[(rq * 4 + j) * DIN + k] * w;
    }
#pragma unroll
    for (int j = 0; j < 4; j++) {
        int r = row0 + rq * 4 + j;
        g_hs[r * DHID + col] = acc[j] * g_dinv[r];
    }
}

// ---------------- gather: agg[i] = hs[i] + sum_{s in in(i)} hs[s]  (64-dim) ----------------
// one warp per node, float2 per lane
__global__ void k_gather(int n) {
    int gt   = blockIdx.x * blockDim.x + threadIdx.x;
    int node = gt >> 5;
    int lane = gt & 31;
    if (node >= n) return;
    const float2* __restrict__ in2 = (const float2*)g_hs;
    float2 acc = in2[node * 32 + lane];        // self-loop term
    int beg = g_offs[node], end = g_offs[node + 1];
    for (int j = beg; j < end; j++) {
        int s = g_csr[j];
        float2 v = in2[s * 32 + lane];
        acc.x += v.x; acc.y += v.y;
    }
    ((float2*)g_agg)[node * 32 + lane] = acc;
}

// ---------------- mid: h1 = agg*dinv + b1 ; zs = relu(h1)*dinv -> g_hs ;
//                  tmp = x + h1 @ Wl + bl ----------------
// block = 256 threads, 8 rows/block
__global__ void k_mid(const float* __restrict__ x,  const float* __restrict__ Wl,
                      const float* __restrict__ b1, const float* __restrict__ bl, int n) {
    __shared__ float Ws[DHID * DOUT];  // 32 KB
    __shared__ float h1s[8 * DHID];    //  2 KB
    int t = threadIdx.x;
    int row0 = blockIdx.x * 8;
    for (int i = t; i < DHID * DOUT; i += 256) Ws[i] = Wl[i];
    for (int idx = t; idx < 8 * DHID; idx += 256) {
        int r = idx >> 6, c = idx & 63;
        int gr = row0 + r;
        float di = g_dinv[gr];
        float h1 = g_agg[gr * DHID + c] * di + b1[c];
        h1s[idx] = h1;
        g_hs[gr * DHID + c] = fmaxf(h1, 0.f) * di;   // zs for conv2
    }
    __syncthreads();
    int col = t & 127;
    int rq  = t >> 7;                  // 0..1, constant per warp
    float acc[4] = {0.f, 0.f, 0.f, 0.f};
#pragma unroll 16
    for (int k = 0; k < DHID; k++) {
        float w = Ws[k * DOUT + col];
#pragma unroll
        for (int j = 0; j < 4; j++)
            acc[j] += h1s[(rq * 4 + j) * DHID + k] * w;
    }
#pragma unroll
    for (int j = 0; j < 4; j++) {
        int gr = row0 + rq * 4 + j;
        g_tmp[gr * DOUT + col] = x[gr * DOUT + col] + acc[j] + bl[col];
    }
}

// ---------------- final: out = tmp + (agg*dinv) @ W2 + b2 ----------------
__global__ void k_final(const float* __restrict__ W2, const float* __restrict__ b2,
                        float* __restrict__ out, int n) {
    __shared__ float Ws[DHID * DOUT];  // 32 KB
    __shared__ float as[8 * DHID];     //  2 KB
    int t = threadIdx.x;
    int row0 = blockIdx.x * 8;
    for (int i = t; i < DHID * DOUT; i += 256) Ws[i] = W2[i];
    for (int idx = t; idx < 8 * DHID; idx += 256) {
        int r = idx >> 6, c = idx & 63;
        int gr = row0 + r;
        as[idx] = g_agg[gr * DHID + c] * g_dinv[gr];
    }
    __syncthreads();
    int col = t & 127;
    int rq  = t >> 7;
    float acc[4] = {0.f, 0.f, 0.f, 0.f};
#pragma unroll 16
    for (int k = 0; k < DHID; k++) {
        float w = Ws[k * DOUT + col];
#pragma unroll
        for (int j = 0; j < 4; j++)
            acc[j] += as[(rq * 4 + j) * DHID + k] * w;
    }
#pragma unroll
    for (int j = 0; j < 4; j++) {
        int gr = row0 + rq * 4 + j;
        out[gr * DOUT + col] = g_tmp[gr * DOUT + col] + acc[j] + b2[col];
    }
}

// ---------------- launch ----------------
extern "C" void kernel_launch(void* const* d_in, const int* in_sizes, int n_in,
                              void* d_out, int out_size) {
    const float* x  = (const float*)d_in[0];
    const int*   ei = (const int*)d_in[1];          // int32! (JAX x64 disabled)
    const float* W1 = (const float*)d_in[2];
    const float* b1 = (const float*)d_in[3];
    const float* Wl = (const float*)d_in[4];
    const float* bl = (const float*)d_in[5];
    const float* W2 = (const float*)d_in[6];
    const float* b2 = (const float*)d_in[7];
    float*       out = (float*)d_out;

    int n = in_sizes[0] / DIN;        // 50000
    int e = in_sizes[1] / 2;          // 800000
    const int* src = ei;
    const int* dst = ei + e;

    int nbN = (n + 255) / 256;        // 196
    int nbE = (e + 255) / 256;        // 3125

    k_init <<<nbN, 256>>>(n);
    k_count<<<nbE, 256>>>(dst, e);
    k_scan1<<<nbN, 256>>>(n);
    k_scan2<<<1,   256>>>(nbN);
    k_scan3<<<nbN, 256>>>(n, e);
    k_fill <<<nbE, 256>>>(src, dst, e);

    k_gemm1 <<<n / 16, 256>>>(x, W1, n);
    k_gather<<<(n * 32) / 256, 256>>>(n);
    k_mid   <<<n / 8, 256>>>(x, Wl, b1, bl, n);
    k_gather<<<(n * 32) / 256, 256>>>(n);
    k_final <<<n / 8, 256>>>(W2, b2, out, n);
}

// round 3
// speedup vs baseline: 1.7640x; 1.7640x over previous
#include <cuda_runtime.h>

#define NN   50000
#define EE   800000
#define DIN  128
#define DHID 64
#define DOUT 128

// ---------------- scratch (static device globals; no allocation) ----------------
__device__ __align__(16) float g_dinv[NN];
__device__ int   g_cnt[NN];
__device__ int   g_cur[NN];
__device__ int   g_offs[NN + 1];
__device__ int   g_csr[EE];
__device__ int   g_part[256];
__device__ int   g_part2[256];
__device__ __align__(16) float g_hs  [NN * DHID];  // pre-agg features (xW1*dinv, then zs)
__device__ __align__(16) float g_agg [NN * DHID];  // gather1 result (kept until final)
__device__ __align__(16) float g_agg2[NN * DHID];  // gather2 result

// ---------------- CSR build ----------------
__global__ void k_init(int n) {
    int i = blockIdx.x * blockDim.x + threadIdx.x;
    if (i < n) { g_cnt[i] = 0; g_cur[i] = 0; }
}

__global__ void k_count(const int* __restrict__ dst, int e) {
    int i = blockIdx.x * blockDim.x + threadIdx.x;
    if (i < e) atomicAdd(&g_cnt[dst[i]], 1);
}

__global__ void k_scan1(int n) {
    __shared__ int sh[256];
    int t = threadIdx.x;
    int i = blockIdx.x * 256 + t;
    int v = (i < n) ? g_cnt[i] : 0;
    sh[t] = v;
    for (int off = 1; off < 256; off <<= 1) {
        __syncthreads();
        int x = (t >= off) ? sh[t - off] : 0;
        __syncthreads();
        sh[t] += x;
    }
    __syncthreads();
    if (i < n) g_offs[i] = sh[t] - v;
    if (t == 255) g_part[blockIdx.x] = sh[255];
}

__global__ void k_scan2(int nb) {
    __shared__ int sh[256];
    int t = threadIdx.x;
    int v = (t < nb) ? g_part[t] : 0;
    sh[t] = v;
    for (int off = 1; off < 256; off <<= 1) {
        __syncthreads();
        int x = (t >= off) ? sh[t - off] : 0;
        __syncthreads();
        sh[t] += x;
    }
    __syncthreads();
    g_part2[t] = sh[t] - v;
}

__global__ void k_scan3(int n, int e) {
    int i = blockIdx.x * 256 + threadIdx.x;
    if (i < n) {
        g_offs[i] += g_part2[blockIdx.x];
        g_dinv[i]  = rsqrtf((float)g_cnt[i] + 1.0f);
    }
    if (i == 0) g_offs[n] = e;
}

__global__ void k_fill(const int* __restrict__ src,
                       const int* __restrict__ dst, int e) {
    int i = blockIdx.x * blockDim.x + threadIdx.x;
    if (i < e) {
        int d = dst[i];
        int p = g_offs[d] + atomicAdd(&g_cur[d], 1);
        g_csr[p] = src[i];
    }
}

// ---------------- GEMM1: g_hs = (x @ W1) * dinv[row] ----------------
// tile 64 rows x 64 cols, 256 threads, 16 outputs/thread (4x4), K chunked by 64
__global__ void k_gemm1(const float* __restrict__ x, const float* __restrict__ W1, int n) {
    __shared__ float xs[64 * 68];     // [r][k] padded, 17408 B
    __shared__ float Ws[64 * 64];     // [k][c] chunk,  16384 B
    int t = threadIdx.x;
    int row0 = blockIdx.x * 64;
    int tx = t & 15;                  // col group: cols tx*4..+3
    int ty = t >> 4;                  // row group: rows ty*4..+3

    float acc[4][4];
#pragma unroll
    for (int j = 0; j < 4; j++)
#pragma unroll
        for (int c = 0; c < 4; c++) acc[j][c] = 0.f;

    for (int kc = 0; kc < DIN; kc += 64) {
        __syncthreads();
        // load x tile [64 rows][64 k] (guard rows >= n by clamping to row0)
        for (int i = t; i < 64 * 64; i += 256) {
            int r = i >> 6, c = i & 63;
            int gr = row0 + r;
            if (gr >= n) gr = row0;
            xs[r * 68 + c] = x[gr * DIN + kc + c];
        }
        // load W1 chunk [64 k][64 c]
        for (int i = t; i < 64 * 64; i += 256) {
            int k = i >> 6, c = i & 63;
            Ws[k * 64 + c] = W1[(kc + k) * DHID + c];
        }
        __syncthreads();
#pragma unroll 16
        for (int k = 0; k < 64; k++) {
            float4 w = *(const float4*)&Ws[k * 64 + tx * 4];
            float a0 = xs[(ty * 4 + 0) * 68 + k];
            float a1 = xs[(ty * 4 + 1) * 68 + k];
            float a2 = xs[(ty * 4 + 2) * 68 + k];
            float a3 = xs[(ty * 4 + 3) * 68 + k];
            acc[0][0] += a0 * w.x; acc[0][1] += a0 * w.y; acc[0][2] += a0 * w.z; acc[0][3] += a0 * w.w;
            acc[1][0] += a1 * w.x; acc[1][1] += a1 * w.y; acc[1][2] += a1 * w.z; acc[1][3] += a1 * w.w;
            acc[2][0] += a2 * w.x; acc[2][1] += a2 * w.y; acc[2][2] += a2 * w.z; acc[2][3] += a2 * w.w;
            acc[3][0] += a3 * w.x; acc[3][1] += a3 * w.y; acc[3][2] += a3 * w.z; acc[3][3] += a3 * w.w;
        }
    }
#pragma unroll
    for (int j = 0; j < 4; j++) {
        int gr = row0 + ty * 4 + j;
        if (gr < n) {
            float di = g_dinv[gr];
            float4 o = make_float4(acc[j][0] * di, acc[j][1] * di, acc[j][2] * di, acc[j][3] * di);
            *(float4*)&g_hs[gr * DHID + tx * 4] = o;
        }
    }
}

// ---------------- gather: out[i] = hs[i] + sum_{s in in(i)} hs[s]  (64-dim) ----------------
// one warp per node, float2 per lane, neighbor loop unrolled x4 for MLP
__global__ void k_gather(int n, int phase) {
    int gt   = blockIdx.x * blockDim.x + threadIdx.x;
    int node = gt >> 5;
    int lane = gt & 31;
    if (node >= n) return;
    const float2* __restrict__ in2 = (const float2*)g_hs;
    float2* __restrict__ out2 = (float2*)(phase ? g_agg2 : g_agg);

    float2 acc = in2[node * 32 + lane];        // self-loop term
    int beg = g_offs[node], end = g_offs[node + 1];
    int j = beg;
    for (; j + 4 <= end; j += 4) {
        int s0 = g_csr[j], s1 = g_csr[j + 1], s2 = g_csr[j + 2], s3 = g_csr[j + 3];
        float2 v0 = in2[s0 * 32 + lane];
        float2 v1 = in2[s1 * 32 + lane];
        float2 v2 = in2[s2 * 32 + lane];
        float2 v3 = in2[s3 * 32 + lane];
        acc.x += v0.x + v1.x + v2.x + v3.x;
        acc.y += v0.y + v1.y + v2.y + v3.y;
    }
    for (; j < end; j++) {
        int s = g_csr[j];
        float2 v = in2[s * 32 + lane];
        acc.x += v.x; acc.y += v.y;
    }
    out2[node * 32 + lane] = acc;
}

// ---------------- relu/scale: g_hs = relu(g_agg*dinv + b1) * dinv  (elementwise) ----------------
__global__ void k_relu(const float* __restrict__ b1, int n) {
    int i = blockIdx.x * blockDim.x + threadIdx.x;     // float4 index
    if (i >= n * (DHID / 4)) return;
    int row = i >> 4;
    int c4  = i & 15;
    float di = g_dinv[row];
    float4 a = *(const float4*)&g_agg[row * DHID + c4 * 4];
    float4 b = *(const float4*)&b1[c4 * 4];
    float4 o;
    o.x = fmaxf(a.x * di + b.x, 0.f) * di;
    o.y = fmaxf(a.y * di + b.y, 0.f) * di;
    o.z = fmaxf(a.z * di + b.z, 0.f) * di;
    o.w = fmaxf(a.w * di + b.w, 0.f) * di;
    *(float4*)&g_hs[row * DHID + c4 * 4] = o;
}

// ---------------- final: out = x + h1@Wl + a2@W2 + bl + b2 ----------------
// h1 = g_agg*dinv + b1  (phase 0, weights Wl)
// a2 = g_agg2*dinv      (phase 1, weights W2)
// tile 32 rows x 128 cols, 256 threads, 16 outputs/thread (4x4)
__global__ void k_final(const float* __restrict__ x,  const float* __restrict__ Wl,
                        const float* __restrict__ W2, const float* __restrict__ b1,
                        const float* __restrict__ bl, const float* __restrict__ b2,
                        float* __restrict__ out, int n) {
    __shared__ float as[32 * 64];      // [r][k]  8192 B
    __shared__ float Ws[64 * 128];     // [k][c] 32768 B
    int t = threadIdx.x;
    int row0 = blockIdx.x * 32;
    int tx = t & 31;                   // cols tx*4..+3
    int ty = t >> 5;                   // rows ty*4..+3

    float acc[4][4];
#pragma unroll
    for (int j = 0; j < 4; j++)
#pragma unroll
        for (int c = 0; c < 4; c++) acc[j][c] = 0.f;

    for (int phase = 0; phase < 2; phase++) {
        const float* A  = phase ? g_agg2 : g_agg;
        const float* Wg = phase ? W2 : Wl;
        __syncthreads();
        // fill A tile: h1 or a2
        for (int i = t; i < 32 * 64; i += 256) {
            int r = i >> 6, c = i & 63;
            int gr = row0 + r;
            if (gr >= n) gr = row0;
            float di = g_dinv[gr];
            float v = A[gr * DHID + c] * di;
            if (phase == 0) v += b1[c];
            as[i] = v;
        }
        // load weights [64][128] via float4
        {
            float4* Ws4 = (float4*)Ws;
            const float4* Wg4 = (const float4*)Wg;
            for (int i = t; i < 64 * 32; i += 256) Ws4[i] = Wg4[i];
        }
        __syncthreads();
#pragma unroll 16
        for (int k = 0; k < 64; k++) {
            float4 w = *(const float4*)&Ws[k * 128 + tx * 4];
            float a0 = as[(ty * 4 + 0) * 64 + k];
            float a1 = as[(ty * 4 + 1) * 64 + k];
            float a2 = as[(ty * 4 + 2) * 64 + k];
            float a3 = as[(ty * 4 + 3) * 64 + k];
            acc[0][0] += a0 * w.x; acc[0][1] += a0 * w.y; acc[0][2] += a0 * w.z; acc[0][3] += a0 * w.w;
            acc[1][0] += a1 * w.x; acc[1][1] += a1 * w.y; acc[1][2] += a1 * w.z; acc[1][3] += a1 * w.w;
            acc[2][0] += a2 * w.x; acc[2][1] += a2 * w.y; acc[2][2] += a2 * w.z; acc[2][3] += a2 * w.w;
            acc[3][0] += a3 * w.x; acc[3][1] += a3 * w.y; acc[3][2] += a3 * w.z; acc[3][3] += a3 * w.w;
        }
    }

    float4 blv = *(const float4*)&bl[tx * 4];
    float4 b2v = *(const float4*)&b2[tx * 4];
#pragma unroll
    for (int j = 0; j < 4; j++) {
        int gr = row0 + ty * 4 + j;
        if (gr < n) {
            float4 xv = *(const float4*)&x[gr * DOUT + tx * 4];
            float4 o;
            o.x = acc[j][0] + xv.x + blv.x + b2v.x;
            o.y = acc[j][1] + xv.y + blv.y + b2v.y;
            o.z = acc[j][2] + xv.z + blv.z + b2v.z;
            o.w = acc[j][3] + xv.w + blv.w + b2v.w;
            *(float4*)&out[gr * DOUT + tx * 4] = o;
        }
    }
}

// ---------------- launch ----------------
extern "C" void kernel_launch(void* const* d_in, const int* in_sizes, int n_in,
                              void* d_out, int out_size) {
    const float* x  = (const float*)d_in[0];
    const int*   ei = (const int*)d_in[1];          // int32 (JAX x64 disabled)
    const float* W1 = (const float*)d_in[2];
    const float* b1 = (const float*)d_in[3];
    const float* Wl = (const float*)d_in[4];
    const float* bl = (const float*)d_in[5];
    const float* W2 = (const float*)d_in[6];
    const float* b2 = (const float*)d_in[7];
    float*       out = (float*)d_out;

    int n = in_sizes[0] / DIN;        // 50000
    int e = in_sizes[1] / 2;          // 800000
    const int* src = ei;
    const int* dst = ei + e;

    int nbN = (n + 255) / 256;        // 196
    int nbE = (e + 255) / 256;        // 3125

    k_init <<<nbN, 256>>>(n);
    k_count<<<nbE, 256>>>(dst, e);
    k_scan1<<<nbN, 256>>>(n);
    k_scan2<<<1,   256>>>(nbN);
    k_scan3<<<nbN, 256>>>(n, e);
    k_fill <<<nbE, 256>>>(src, dst, e);

    k_gemm1 <<<(n + 63) / 64, 256>>>(x, W1, n);
    k_gather<<<(n * 32 + 255) / 256, 256>>>(n, 0);
    k_relu  <<<(n * (DHID / 4) + 255) / 256, 256>>>(b1, n);
    k_gather<<<(n * 32 + 255) / 256, 256>>>(n, 1);
    k_final <<<(n + 31) / 32, 256>>>(x, Wl, W2, b1, bl, b2, out, n);
}